// round 15
// baseline (speedup 1.0000x reference)
#include <cuda_runtime.h>
#include <cuda_fp16.h>
#include <math.h>
#include <stdint.h>

#define NB       128
#define NB2      (NB*NB)
#define KC       128              /* points per chunk = GEMM K tile   */
#define GRID     296              /* 2 CTAs per SM                    */
#define NTHREADS 256
#define RWIN     5
#define WBINS    11
#define SP       136              /* padded row stride in halfs (272B: conflict-free ldmatrix) */
#define TILE_BYTES (NB * SP * 2)  /* 34816 B per operand tile */
#define SMEM_TOTAL (2 * TILE_BYTES)
#define NSLICE   8
#define CPS      (GRID / NSLICE)  /* 37 partials per slice */

__device__ float g_part[GRID * NB2];   /* per-CTA partial histograms */
__device__ float g_red[NSLICE * NB2];  /* slice-reduced histograms   */
__device__ float g_csum[GRID];         /* per-CTA total mass         */

/* ------------ PTX helpers ------------ */
__device__ __forceinline__ uint32_t smem_u32(const void* p) {
    uint32_t a;
    asm("{ .reg .u64 t; cvta.to.shared.u64 t, %1; cvt.u32.u64 %0, t; }" : "=r"(a) : "l"(p));
    return a;
}
__device__ __forceinline__ void ldsm4(uint32_t& r0, uint32_t& r1, uint32_t& r2, uint32_t& r3,
                                      uint32_t addr) {
    asm volatile("ldmatrix.sync.aligned.m8n8.x4.shared.b16 {%0,%1,%2,%3}, [%4];"
                 : "=r"(r0), "=r"(r1), "=r"(r2), "=r"(r3) : "r"(addr));
}
__device__ __forceinline__ void mma16816(float* c,
                                         uint32_t a0, uint32_t a1, uint32_t a2, uint32_t a3,
                                         uint32_t b0, uint32_t b1) {
    asm volatile("mma.sync.aligned.m16n8k16.row.col.f32.f16.f16.f32 "
                 "{%0,%1,%2,%3}, {%4,%5,%6,%7}, {%8,%9}, {%0,%1,%2,%3};"
                 : "+f"(c[0]), "+f"(c[1]), "+f"(c[2]), "+f"(c[3])
                 : "r"(a0), "r"(a1), "r"(a2), "r"(a3), "r"(b0), "r"(b1));
}
__device__ __forceinline__ void sts16(uint32_t addr, unsigned short v) {
    asm volatile("st.shared.b16 [%0], %1;" :: "r"(addr), "h"(v) : "memory");
}
__device__ __forceinline__ uint32_t packh2(float a, float b) {
    __half2 h = __floats2half2_rn(a, b);
    return *reinterpret_cast<uint32_t*>(&h);
}

/* ------------ main kernel: persistent per-CTA GEMM, 64x32 warp tiles,
   next-chunk weights computed under the MMA shadow ------------ */
__global__ void __launch_bounds__(NTHREADS, 2) hist_mma_kernel(
    const float* __restrict__ x, int n,
    const float* __restrict__ ex, const float* __restrict__ ey)
{
    extern __shared__ char smem[];
    const uint32_t sbase = smem_u32(smem);
    const int tid  = threadIdx.x;
    const int wid  = tid >> 5;
    const int lane = tid & 31;

    /* zero both operand tiles (incl. padding) */
    {
        uint4 z4 = make_uint4(0, 0, 0, 0);
        uint4* t = (uint4*)smem;
        #pragma unroll
        for (int i = tid; i < SMEM_TOTAL / 16; i += NTHREADS) t[i] = z4;
    }

    /* producer-role constants: thread -> (point-in-chunk, operand axis) */
    const int p    = tid & (KC - 1);
    const int opnd = tid >> 7;                 /* 0 = x-axis tile (A), 1 = y-axis tile (B) */
    const uint32_t mytile = sbase + (uint32_t)opnd * TILE_BYTES;

    const float e0 = opnd ? ey[0] : ex[0];
    const float dv = (opnd ? ey[1] : ex[1]) - e0;
    const float inv_d = 1.0f / dv;
    const float is = 1.0f / (dv * 1.41421356237309515f);

    /* MMA-role constants: warp grid 2(M) x 4(N); warp tile 64 rows x 32 cols */
    const int mw = wid >> 2;
    const int nw = wid & 3;
    const uint32_t arow  = (uint32_t)(64 * mw + (lane & 15));
    const uint32_t selA  = (uint32_t)(((lane >> 4) & 1) << 3);
    const uint32_t aBase = sbase + (arow * SP + selA) * 2;
    const uint32_t brow  = (uint32_t)(32 * nw + (lane & 7) + (((lane >> 4) & 1) << 3));
    const uint32_t selB  = (uint32_t)(((lane >> 3) & 1) << 3);
    const uint32_t bBase = sbase + TILE_BYTES + (brow * SP + selB) * 2;

    float acc[64];
    #pragma unroll
    for (int i = 0; i < 64; i++) acc[i] = 0.0f;

    const int nch = (n + KC - 1) / KC;
    int prev_lo = 0;

    /* staged weights for the chunk about to be written: 6 packed half2 + lo */
    uint32_t wpk[6];
    int lo_w = 0;

    /* prologue: load + compute W(chunk c0) */
    int c = blockIdx.x;
    {
        int g = c * KC + p;
        bool v = (g < n);
        float u = v ? x[g * 6 + opnd] : 0.0f;
        int ci = (int)floorf((u - e0) * inv_d);
        int lo = min(max(ci - RWIN, 0), NB - WBINS);
        float a0 = (fmaf((float)lo, dv, e0) - u) * is;
        float zp = erff(a0);
        #pragma unroll
        for (int jj = 0; jj < 6; jj++) {
            float z1 = erff(fmaf((float)(2 * jj + 1), 0.70710678118654752f, a0));
            float z2 = erff(fmaf((float)(2 * jj + 2), 0.70710678118654752f, a0));
            float w0 = v ? 0.5f * (z1 - zp) : 0.0f;
            float w1 = (jj < 5 && v) ? 0.5f * (z2 - z1) : 0.0f;
            wpk[jj] = packh2(w0, w1);
            zp = z2;
        }
        lo_w = lo;
    }
    /* prefetch coord for chunk c + GRID */
    float u_nxt = 0.0f;
    bool  v_nxt = false;
    {
        int cn = c + GRID;
        if (cn < nch) {
            int g = cn * KC + p;
            v_nxt = (g < n);
            if (v_nxt) u_nxt = x[g * 6 + opnd];
        }
    }
    __syncthreads();

    while (c < nch) {
        /* ---- STS phase: clear previous window, unpack + write staged weights ---- */
        #pragma unroll
        for (int j = 0; j < WBINS; j++)
            sts16(mytile + (uint32_t)((prev_lo + j) * SP + p) * 2, 0);
        #pragma unroll
        for (int jj = 0; jj < 6; jj++) {
            uint32_t pk = wpk[jj];
            sts16(mytile + (uint32_t)((lo_w + 2 * jj) * SP + p) * 2,
                  (unsigned short)(pk & 0xffffu));
            if (jj < 5)
                sts16(mytile + (uint32_t)((lo_w + 2 * jj + 1) * SP + p) * 2,
                      (unsigned short)(pk >> 16));
        }
        prev_lo = lo_w;

        __syncthreads();

        /* ---- MMA region: HMMA stream + (hidden) next-chunk weight computation ---- */
        const int cn = c + GRID;

        /* prefetch coord for chunk cn + GRID */
        float u2 = 0.0f;
        bool  v2 = false;
        {
            int cnn = cn + GRID;
            if (cnn < nch) {
                int g = cnn * KC + p;
                v2 = (g < n);
                if (v2) u2 = x[g * 6 + opnd];
            }
        }

        /* MMA: acc(64x32) += A(64xK) * B^T(Kx32), K = 128 */
        #pragma unroll
        for (int k8 = 0; k8 < 8; k8++) {
            uint32_t b0r[4], b1r[4];
            ldsm4(b0r[0], b0r[1], b0r[2], b0r[3], bBase + (uint32_t)k8 * 32);
            ldsm4(b1r[0], b1r[1], b1r[2], b1r[3],
                  bBase + (uint32_t)(16 * SP * 2) + (uint32_t)k8 * 32);
            #pragma unroll
            for (int mt = 0; mt < 4; mt++) {
                uint32_t a0r, a1r, a2r, a3r;
                ldsm4(a0r, a1r, a2r, a3r,
                      aBase + (uint32_t)mt * (16 * SP * 2) + (uint32_t)k8 * 32);
                mma16816(acc + (mt * 4 + 0) * 4, a0r, a1r, a2r, a3r, b0r[0], b0r[1]);
                mma16816(acc + (mt * 4 + 1) * 4, a0r, a1r, a2r, a3r, b0r[2], b0r[3]);
                mma16816(acc + (mt * 4 + 2) * 4, a0r, a1r, a2r, a3r, b1r[0], b1r[1]);
                mma16816(acc + (mt * 4 + 3) * 4, a0r, a1r, a2r, a3r, b1r[2], b1r[3]);
            }
        }

        /* compute W(cn) — independent fma/MUFU chains, scheduled into HMMA gaps */
        if (cn < nch) {
            int ci = (int)floorf((u_nxt - e0) * inv_d);
            int lo = min(max(ci - RWIN, 0), NB - WBINS);
            float a0 = (fmaf((float)lo, dv, e0) - u_nxt) * is;
            float zp = erff(a0);
            #pragma unroll
            for (int jj = 0; jj < 6; jj++) {
                float z1 = erff(fmaf((float)(2 * jj + 1), 0.70710678118654752f, a0));
                float z2 = erff(fmaf((float)(2 * jj + 2), 0.70710678118654752f, a0));
                float w0 = v_nxt ? 0.5f * (z1 - zp) : 0.0f;
                float w1 = (jj < 5 && v_nxt) ? 0.5f * (z2 - z1) : 0.0f;
                wpk[jj] = packh2(w0, w1);
                zp = z2;
            }
            lo_w = lo;
        }

        __syncthreads();
        u_nxt = u2; v_nxt = v2; c = cn;
    }

    /* ---- epilogue: dump register accumulator + per-CTA total mass ---- */
    float* dst = g_part + (size_t)blockIdx.x * NB2;
    const int grp = lane >> 2;
    const int qc  = (lane & 3) * 2;
    float tsum = 0.0f;
    #pragma unroll
    for (int mt = 0; mt < 4; mt++) {
        #pragma unroll
        for (int nt = 0; nt < 2; nt++) {
            #pragma unroll
            for (int half = 0; half < 2; half++) {
                float* cacc = acc + ((mt * 2 + nt) * 2 + half) * 4;
                int row0 = 64 * mw + 16 * mt + grp;
                int col  = 32 * nw + 16 * nt + 8 * half + qc;
                *(float2*)(dst + row0 * NB + col)       = make_float2(cacc[0], cacc[1]);
                *(float2*)(dst + (row0 + 8) * NB + col) = make_float2(cacc[2], cacc[3]);
                tsum += cacc[0] + cacc[1] + cacc[2] + cacc[3];
            }
        }
    }
    #pragma unroll
    for (int o = 16; o > 0; o >>= 1) tsum += __shfl_down_sync(0xffffffffu, tsum, o);
    __shared__ float ws[8];
    if (lane == 0) ws[wid] = tsum;
    __syncthreads();
    if (tid < 8) {
        float t = ws[tid];
        #pragma unroll
        for (int o = 4; o > 0; o >>= 1) t += __shfl_down_sync(0xffu, t, o);
        if (tid == 0) g_csum[blockIdx.x] = t;
    }
}

/* ------------ stage 2: slice-parallel partial reduction (512 blocks) ------------ */
__global__ void __launch_bounds__(256) reduce_split_kernel() {
    const int s    = blockIdx.x & (NSLICE - 1);
    const int cg   = blockIdx.x >> 3;
    const int cell = cg * 256 + threadIdx.x;
    const float* src = g_part + (size_t)(s * CPS) * NB2 + cell;
    float sum = 0.0f;
    #pragma unroll
    for (int i = 0; i < CPS; i++) sum += src[(size_t)i * NB2];
    g_red[s * NB2 + cell] = sum;
}

/* ------------ stage 3: fold slices + normalize ------------ */
__global__ void __launch_bounds__(256) final_kernel(
    const float* __restrict__ ex, const float* __restrict__ ey, float* __restrict__ out)
{
    float t = g_csum[threadIdx.x];
    if (threadIdx.x < GRID - 256) t += g_csum[threadIdx.x + 256];
    #pragma unroll
    for (int o = 16; o > 0; o >>= 1) t += __shfl_down_sync(0xffffffffu, t, o);
    __shared__ float ws[8];
    __shared__ float sc_s;
    if ((threadIdx.x & 31) == 0) ws[threadIdx.x >> 5] = t;
    __syncthreads();
    if (threadIdx.x < 8) {
        float q = ws[threadIdx.x];
        #pragma unroll
        for (int o = 4; o > 0; o >>= 1) q += __shfl_down_sync(0xffu, q, o);
        if (threadIdx.x == 0) {
            float dxv = ex[1] - ex[0];
            float dyv = ey[1] - ey[0];
            sc_s = 1.0f / (q * dxv * dyv);
        }
    }
    __syncthreads();

    const int cell = blockIdx.x * 256 + threadIdx.x;
    float v = 0.0f;
    #pragma unroll
    for (int s = 0; s < NSLICE; s++) v += g_red[s * NB2 + cell];
    out[cell] = v * sc_s;
}

extern "C" void kernel_launch(void* const* d_in, const int* in_sizes, int n_in,
                              void* d_out, int out_size)
{
    const float* x  = (const float*)d_in[0];
    const float* ex = (const float*)d_in[1];
    const float* ey = (const float*)d_in[2];
    int n = in_sizes[0] / 6;

    cudaFuncSetAttribute(hist_mma_kernel,
                         cudaFuncAttributeMaxDynamicSharedMemorySize, SMEM_TOTAL);

    hist_mma_kernel<<<GRID, NTHREADS, SMEM_TOTAL>>>(x, n, ex, ey);
    reduce_split_kernel<<<(NB2 / 256) * NSLICE, 256>>>();
    final_kernel<<<NB2 / 256, 256>>>(ex, ey, (float*)d_out);
}

// round 17
// speedup vs baseline: 1.0613x; 1.0613x over previous
#include <cuda_runtime.h>
#include <cuda_fp16.h>
#include <math.h>
#include <stdint.h>

#define NB       128
#define NB2      (NB*NB)
#define KC       128              /* points per chunk = GEMM K tile   */
#define GRID     148              /* 1 CTA per SM                     */
#define NTHREADS 512              /* 8 MMA warps + 8 producer warps   */
#define RWIN     5
#define WBINS    11
#define SP       136              /* padded row stride in halfs (272B: conflict-free ldmatrix) */
#define TILE_BYTES (NB * SP * 2)  /* 34816 B per operand tile */
#define BUF_BYTES  (2 * TILE_BYTES)
#define SMEM_TOTAL (2 * BUF_BYTES)   /* 139264 B: two (A,B) buffer pairs */
#define NSLICE   4
#define CPS      (GRID / NSLICE)  /* 37 partials per slice */

__device__ float g_part[GRID * NB2];   /* per-CTA partial histograms */
__device__ float g_red[NSLICE * NB2];  /* slice-reduced histograms   */
__device__ float g_csum[GRID];         /* per-CTA total mass         */

/* ------------ PTX helpers ------------ */
__device__ __forceinline__ uint32_t smem_u32(const void* p) {
    uint32_t a;
    asm("{ .reg .u64 t; cvta.to.shared.u64 t, %1; cvt.u32.u64 %0, t; }" : "=r"(a) : "l"(p));
    return a;
}
__device__ __forceinline__ void ldsm4(uint32_t& r0, uint32_t& r1, uint32_t& r2, uint32_t& r3,
                                      uint32_t addr) {
    asm volatile("ldmatrix.sync.aligned.m8n8.x4.shared.b16 {%0,%1,%2,%3}, [%4];"
                 : "=r"(r0), "=r"(r1), "=r"(r2), "=r"(r3) : "r"(addr));
}
__device__ __forceinline__ void mma16816(float* c,
                                         uint32_t a0, uint32_t a1, uint32_t a2, uint32_t a3,
                                         uint32_t b0, uint32_t b1) {
    asm volatile("mma.sync.aligned.m16n8k16.row.col.f32.f16.f16.f32 "
                 "{%0,%1,%2,%3}, {%4,%5,%6,%7}, {%8,%9}, {%0,%1,%2,%3};"
                 : "+f"(c[0]), "+f"(c[1]), "+f"(c[2]), "+f"(c[3])
                 : "r"(a0), "r"(a1), "r"(a2), "r"(a3), "r"(b0), "r"(b1));
}
__device__ __forceinline__ void sts16(uint32_t addr, unsigned short v) {
    asm volatile("st.shared.b16 [%0], %1;" :: "r"(addr), "h"(v) : "memory");
}

/* ------------ main kernel: warp-specialized producer/consumer pipeline ------------ */
__global__ void __launch_bounds__(NTHREADS, 1) hist_mma_kernel(
    const float* __restrict__ x, int n,
    const float* __restrict__ ex, const float* __restrict__ ey)
{
    extern __shared__ char smem[];
    const uint32_t sbase = smem_u32(smem);
    const int tid  = threadIdx.x;
    const int wid  = tid >> 5;
    const int lane = tid & 31;
    const bool is_mma = (wid < 8);

    /* zero both buffer pairs (incl. padding) */
    {
        uint4 z4 = make_uint4(0, 0, 0, 0);
        uint4* t = (uint4*)smem;
        #pragma unroll
        for (int i = tid; i < SMEM_TOTAL / 16; i += NTHREADS) t[i] = z4;
    }

    const int nch    = (n + KC - 1) / KC;
    const int bid    = blockIdx.x;
    const int my_nch = (nch - bid + GRID - 1) / GRID;   /* chunks this CTA handles (>=1) */

    /* ---------------- producer-role constants (warps 8..15) ---------------- */
    const int p    = tid & (KC - 1);
    const int opnd = (tid >> 7) & 1;           /* 0 = x-axis tile (A), 1 = y-axis tile (B) */
    const uint32_t ptile0 = sbase + (uint32_t)opnd * TILE_BYTES;

    const float e0 = opnd ? ey[0] : ex[0];
    const float dv = (opnd ? ey[1] : ex[1]) - e0;
    const float inv_d = 1.0f / dv;
    const float is = 1.0f / (dv * 1.41421356237309515f);

    /* ---------------- MMA-role constants (warps 0..7): 2(M) x 4(N), 64x32 tiles ---------------- */
    const int mw = (wid >> 2) & 1;
    const int nw = wid & 3;
    const uint32_t arow  = (uint32_t)(64 * mw + (lane & 15));
    const uint32_t selA  = (uint32_t)(((lane >> 4) & 1) << 3);
    const uint32_t aBase0 = sbase + (arow * SP + selA) * 2;
    const uint32_t brow  = (uint32_t)(32 * nw + (lane & 7) + (((lane >> 4) & 1) << 3));
    const uint32_t selB  = (uint32_t)(((lane >> 3) & 1) << 3);
    const uint32_t bBase0 = sbase + TILE_BYTES + (brow * SP + selB) * 2;

    float acc[64];
    #pragma unroll
    for (int i = 0; i < 64; i++) acc[i] = 0.0f;

    int prev_lo[2] = {0, 0};
    float u_cur = 0.0f, u_nxt = 0.0f;
    bool  v_cur = false, v_nxt = false;

    __syncthreads();   /* tiles zeroed before producer prologue writes */

    if (!is_mma) {
        /* prologue: produce chunk bid into buffer 0 */
        {
            int g = bid * KC + p;
            v_cur = (g < n);
            if (v_cur) u_cur = x[g * 6 + opnd];

            int ci = (int)floorf((u_cur - e0) * inv_d);
            int lo = min(max(ci - RWIN, 0), NB - WBINS);
            float a0 = (fmaf((float)lo, dv, e0) - u_cur) * is;
            float z[WBINS + 1];
            #pragma unroll
            for (int k = 0; k <= WBINS; k++)
                z[k] = erff(fmaf((float)k, 0.70710678118654752f, a0));
            #pragma unroll
            for (int j = 0; j < WBINS; j++) {
                float w = v_cur ? 0.5f * (z[j + 1] - z[j]) : 0.0f;
                sts16(ptile0 + (uint32_t)((lo + j) * SP + p) * 2,
                      __half_as_ushort(__float2half_rn(w)));
            }
            prev_lo[0] = lo;
        }
        /* prefetch coord for chunk bid + GRID */
        if (1 < my_nch) {
            int g = (bid + GRID) * KC + p;
            v_nxt = (g < n);
            if (v_nxt) u_nxt = x[g * 6 + opnd];
        }
    }

    for (int it = 0; it < my_nch; it++) {
        __syncthreads();   /* buffer it&1 is ready; buffer (it+1)&1 is free */

        if (is_mma) {
            /* ---- consume buffer it&1: acc(64x32) += A(64xK) * B^T(Kx32) ---- */
            const uint32_t off = (uint32_t)(it & 1) * BUF_BYTES;
            const uint32_t aB = aBase0 + off;
            const uint32_t bB = bBase0 + off;
            #pragma unroll
            for (int k8 = 0; k8 < 8; k8++) {
                uint32_t b0r[4], b1r[4];
                ldsm4(b0r[0], b0r[1], b0r[2], b0r[3], bB + (uint32_t)k8 * 32);
                ldsm4(b1r[0], b1r[1], b1r[2], b1r[3],
                      bB + (uint32_t)(16 * SP * 2) + (uint32_t)k8 * 32);
                #pragma unroll
                for (int mt = 0; mt < 4; mt++) {
                    uint32_t a0r, a1r, a2r, a3r;
                    ldsm4(a0r, a1r, a2r, a3r,
                          aB + (uint32_t)mt * (16 * SP * 2) + (uint32_t)k8 * 32);
                    mma16816(acc + (mt * 4 + 0) * 4, a0r, a1r, a2r, a3r, b0r[0], b0r[1]);
                    mma16816(acc + (mt * 4 + 1) * 4, a0r, a1r, a2r, a3r, b0r[2], b0r[3]);
                    mma16816(acc + (mt * 4 + 2) * 4, a0r, a1r, a2r, a3r, b1r[0], b1r[1]);
                    mma16816(acc + (mt * 4 + 3) * 4, a0r, a1r, a2r, a3r, b1r[2], b1r[3]);
                }
            }
        } else if (it + 1 < my_nch) {
            /* ---- produce chunk bid+(it+1)*GRID into buffer (it+1)&1 ---- */
            const int nb = (it + 1) & 1;
            const uint32_t ptile = ptile0 + (uint32_t)nb * BUF_BYTES;
            const int pl = prev_lo[nb];
            #pragma unroll
            for (int j = 0; j < WBINS; j++)
                sts16(ptile + (uint32_t)((pl + j) * SP + p) * 2, 0);

            int ci = (int)floorf((u_nxt - e0) * inv_d);
            int lo = min(max(ci - RWIN, 0), NB - WBINS);
            float a0 = (fmaf((float)lo, dv, e0) - u_nxt) * is;
            float z[WBINS + 1];
            #pragma unroll
            for (int k = 0; k <= WBINS; k++)
                z[k] = erff(fmaf((float)k, 0.70710678118654752f, a0));
            bool vv = v_nxt;
            #pragma unroll
            for (int j = 0; j < WBINS; j++) {
                float w = vv ? 0.5f * (z[j + 1] - z[j]) : 0.0f;
                sts16(ptile + (uint32_t)((lo + j) * SP + p) * 2,
                      __half_as_ushort(__float2half_rn(w)));
            }
            prev_lo[nb] = lo;

            /* prefetch coord for chunk bid+(it+2)*GRID */
            v_nxt = false;
            if (it + 2 < my_nch) {
                int g = (bid + (it + 2) * GRID) * KC + p;
                v_nxt = (g < n);
                if (v_nxt) u_nxt = x[g * 6 + opnd];
            }
        }
    }

    /* ---- epilogue: MMA warps dump accumulator + per-CTA total mass ---- */
    __shared__ float ws[8];
    if (is_mma) {
        float* dst = g_part + (size_t)bid * NB2;
        const int grp = lane >> 2;
        const int qc  = (lane & 3) * 2;
        float tsum = 0.0f;
        #pragma unroll
        for (int mt = 0; mt < 4; mt++) {
            #pragma unroll
            for (int nt = 0; nt < 2; nt++) {
                #pragma unroll
                for (int half = 0; half < 2; half++) {
                    float* cacc = acc + ((mt * 2 + nt) * 2 + half) * 4;
                    int row0 = 64 * mw + 16 * mt + grp;
                    int col  = 32 * nw + 16 * nt + 8 * half + qc;
                    *(float2*)(dst + row0 * NB + col)       = make_float2(cacc[0], cacc[1]);
                    *(float2*)(dst + (row0 + 8) * NB + col) = make_float2(cacc[2], cacc[3]);
                    tsum += cacc[0] + cacc[1] + cacc[2] + cacc[3];
                }
            }
        }
        #pragma unroll
        for (int o = 16; o > 0; o >>= 1) tsum += __shfl_down_sync(0xffffffffu, tsum, o);
        if (lane == 0) ws[wid] = tsum;
    }
    __syncthreads();
    if (tid < 8) {
        float t = ws[tid];
        #pragma unroll
        for (int o = 4; o > 0; o >>= 1) t += __shfl_down_sync(0xffu, t, o);
        if (tid == 0) g_csum[bid] = t;
    }
}

/* ------------ stage 2: slice-parallel partial reduction (256 blocks) ------------ */
__global__ void __launch_bounds__(256) reduce_split_kernel() {
    const int s    = blockIdx.x & (NSLICE - 1);
    const int cg   = blockIdx.x >> 2;
    const int cell = cg * 256 + threadIdx.x;
    const float* src = g_part + (size_t)(s * CPS) * NB2 + cell;
    float sum = 0.0f;
    #pragma unroll
    for (int i = 0; i < CPS; i++) sum += src[(size_t)i * NB2];
    g_red[s * NB2 + cell] = sum;
}

/* ------------ stage 3: fold slices + normalize ------------ */
__global__ void __launch_bounds__(256) final_kernel(
    const float* __restrict__ ex, const float* __restrict__ ey, float* __restrict__ out)
{
    float t = (threadIdx.x < GRID) ? g_csum[threadIdx.x] : 0.0f;
    #pragma unroll
    for (int o = 16; o > 0; o >>= 1) t += __shfl_down_sync(0xffffffffu, t, o);
    __shared__ float ws[8];
    __shared__ float sc_s;
    if ((threadIdx.x & 31) == 0) ws[threadIdx.x >> 5] = t;
    __syncthreads();
    if (threadIdx.x < 8) {
        float q = ws[threadIdx.x];
        #pragma unroll
        for (int o = 4; o > 0; o >>= 1) q += __shfl_down_sync(0xffu, q, o);
        if (threadIdx.x == 0) {
            float dxv = ex[1] - ex[0];
            float dyv = ey[1] - ey[0];
            sc_s = 1.0f / (q * dxv * dyv);
        }
    }
    __syncthreads();

    const int cell = blockIdx.x * 256 + threadIdx.x;
    float v = 0.0f;
    #pragma unroll
    for (int s = 0; s < NSLICE; s++) v += g_red[s * NB2 + cell];
    out[cell] = v * sc_s;
}

extern "C" void kernel_launch(void* const* d_in, const int* in_sizes, int n_in,
                              void* d_out, int out_size)
{
    const float* x  = (const float*)d_in[0];
    const float* ex = (const float*)d_in[1];
    const float* ey = (const float*)d_in[2];
    int n = in_sizes[0] / 6;

    cudaFuncSetAttribute(hist_mma_kernel,
                         cudaFuncAttributeMaxDynamicSharedMemorySize, SMEM_TOTAL);

    hist_mma_kernel<<<GRID, NTHREADS, SMEM_TOTAL>>>(x, n, ex, ey);
    reduce_split_kernel<<<(NB2 / 256) * NSLICE, 256>>>();
    final_kernel<<<NB2 / 256, 256>>>(ex, ey, (float*)d_out);
}